// round 2
// baseline (speedup 1.0000x reference)
#include <cuda_runtime.h>

#define NMAX 100000
#define EPSF 1e-5f

// Scratch for the q/k/v projections (device globals: allocation-free).
__device__ float g_xq[NMAX * 64];
__device__ float g_xk[NMAX * 64];
__device__ float g_xv[NMAX * 64];

// ---------------------------------------------------------------------------
// Kernel A: xq = x@Wq.T+bq, xk = x@Wk.T+bk, xv = x@Wv.T+bv
// Persistent blocks, 192 threads. Weights (all three, transposed to [c][o3])
// live in 48KB shared. Thread computes a 4-point x 4-channel register tile.
// ---------------------------------------------------------------------------
__global__ __launch_bounds__(192) void proj_kernel(
    const float* __restrict__ x,
    const float* __restrict__ Wq, const float* __restrict__ bq,
    const float* __restrict__ Wk, const float* __restrict__ bk,
    const float* __restrict__ Wv, const float* __restrict__ bv,
    int N)
{
    __shared__ __align__(16) float Wt[64 * 192];   // Wt[c][o3], o3: 0..63 q, 64..127 k, 128..191 v
    int t = threadIdx.x;
    for (int i = t; i < 64 * 64; i += 192) {
        int o = i >> 6, c = i & 63;
        Wt[c * 192 + o]       = Wq[i];
        Wt[c * 192 + 64 + o]  = Wk[i];
        Wt[c * 192 + 128 + o] = Wv[i];
    }
    __syncthreads();

    int cg = t % 48;          // channel group: outputs 4*cg .. 4*cg+3
    int pg = t / 48;          // point group: 4 points
    int o0 = 4 * cg;
    const float* bsel = (o0 < 64) ? bq : (o0 < 128) ? bk : bv;
    float* dsel = (o0 < 64) ? g_xq : (o0 < 128) ? g_xk : g_xv;
    int oc = o0 & 63;
    float bb0 = bsel[oc], bb1 = bsel[oc + 1], bb2 = bsel[oc + 2], bb3 = bsel[oc + 3];

    int numTiles = (N + 15) >> 4;
    for (int tile = blockIdx.x; tile < numTiles; tile += gridDim.x) {
        int pbase = tile * 16 + pg * 4;
        float acc[4][4];
        #pragma unroll
        for (int a = 0; a < 4; a++)
            #pragma unroll
            for (int b = 0; b < 4; b++) acc[a][b] = 0.f;

        #pragma unroll 4
        for (int c4 = 0; c4 < 16; c4++) {
            float wtv[4][4];
            #pragma unroll
            for (int k = 0; k < 4; k++) {
                float4 w4 = *(const float4*)&Wt[(4 * c4 + k) * 192 + o0];
                wtv[k][0] = w4.x; wtv[k][1] = w4.y; wtv[k][2] = w4.z; wtv[k][3] = w4.w;
            }
            #pragma unroll
            for (int pp = 0; pp < 4; pp++) {
                int pt = pbase + pp;
                int ptc = (pt < N) ? pt : 0;      // clamp: load is safe, store is guarded
                float4 x4 = *(const float4*)&x[(long long)ptc * 64 + 4 * c4];
                float xv_[4] = {x4.x, x4.y, x4.z, x4.w};
                #pragma unroll
                for (int k = 0; k < 4; k++)
                    #pragma unroll
                    for (int j = 0; j < 4; j++)
                        acc[pp][j] = fmaf(xv_[k], wtv[k][j], acc[pp][j]);
            }
        }
        #pragma unroll
        for (int pp = 0; pp < 4; pp++) {
            int pt = pbase + pp;
            if (pt < N) {
                float4 v = make_float4(acc[pp][0] + bb0, acc[pp][1] + bb1,
                                       acc[pp][2] + bb2, acc[pp][3] + bb3);
                *(float4*)&dsel[(long long)pt * 64 + oc] = v;
            }
        }
    }
}

// ---------------------------------------------------------------------------
// Kernel B: fused gather + positional MLP + attention-weight MLP + softmax +
// weighted reduce. 256 threads = 8 warps = 16 points per block.
// Phase 1: lane = neighbor (16 lanes per point). Phase 2: lane = 4 channels.
// ---------------------------------------------------------------------------
__global__ __launch_bounds__(256) void attn_kernel(
    const float* __restrict__ p, const int* __restrict__ idx,
    const float* __restrict__ pw1g, const float* __restrict__ pb1g,
    const float* __restrict__ pbng, const float* __restrict__ pbnb,
    const float* __restrict__ pbnm, const float* __restrict__ pbnv,
    const float* __restrict__ pw2g, const float* __restrict__ pb2g,
    const float* __restrict__ bn1g, const float* __restrict__ bn1b,
    const float* __restrict__ bn1m, const float* __restrict__ bn1v,
    const float* __restrict__ w1g,  const float* __restrict__ wb1g,
    const float* __restrict__ bn2g, const float* __restrict__ bn2b,
    const float* __restrict__ bn2m, const float* __restrict__ bn2v,
    const float* __restrict__ w2g,  const float* __restrict__ wb2g,
    float* __restrict__ out, int N)
{
    __shared__ __align__(16) float a1s[64], b1s[64];                  // folded BN1
    __shared__ __align__(16) float pw20s[64], pw21s[64], pw22s[64], pb2s[64];
    __shared__ __align__(16) float w1s[512];                          // w_w1 [o][c]
    __shared__ float w2s[64], a2s[8], b2s[8], wb1s[8], wb2s[8];
    __shared__ float pw1s[9], pb1s[3], pas[3], pbfs[3];
    __shared__ __align__(16) float xqs[16][64];
    __shared__ __align__(16) float wexps[16][16][8];
    __shared__ float hs[16][16][3];
    __shared__ int   idxs[16][16];
    __shared__ float pns[16][3];

    int t = threadIdx.x;
    int n0 = blockIdx.x * 16;

    if (t < 64) {
        float a = bn1g[t] * rsqrtf(bn1v[t] + EPSF);
        a1s[t] = a; b1s[t] = bn1b[t] - bn1m[t] * a;
        pw20s[t] = pw2g[t * 3 + 0];
        pw21s[t] = pw2g[t * 3 + 1];
        pw22s[t] = pw2g[t * 3 + 2];
        pb2s[t]  = pb2g[t];
        w2s[t]   = w2g[t];
    }
    for (int i = t; i < 512; i += 256) w1s[i] = w1g[i];
    if (t < 8) {
        float a = bn2g[t] * rsqrtf(bn2v[t] + EPSF);
        a2s[t] = a; b2s[t] = bn2b[t] - bn2m[t] * a;
        wb1s[t] = wb1g[t]; wb2s[t] = wb2g[t];
    }
    if (t < 9) pw1s[t] = pw1g[t];
    if (t < 3) {
        pb1s[t] = pb1g[t];
        float a = pbng[t] * rsqrtf(pbnv[t] + EPSF);
        pas[t] = a; pbfs[t] = pbnb[t] - pbnm[t] * a;
    }
    for (int i = t; i < 16 * 64; i += 256) {
        int pp = i >> 6, c = i & 63;
        int n = n0 + pp;
        ((float*)xqs)[i] = (n < N) ? g_xq[(long long)n * 64 + c] : 0.f;
    }
    {
        int pp = t >> 4, j = t & 15;
        int n = n0 + pp;
        int v = (n < N) ? idx[(long long)n * 16 + j] : 0;
        // defensive clamp: guarantees no OOB even if index dtype assumption is wrong
        v = (v < 0) ? 0 : ((v >= N) ? N - 1 : v);
        idxs[pp][j] = v;
    }
    if (t < 48) {
        int pp = t / 3, d = t % 3;
        int n = n0 + pp;
        pns[pp][d] = (n < N) ? p[(long long)n * 3 + d] : 0.f;
    }
    __syncthreads();

    int lane = t & 31;
    int jj = lane & 15;                 // neighbor index (phase 1)
    int lp = (t >> 5) * 2 + (lane >> 4);// local point 0..15
    int n = n0 + lp;

    // ---- Phase 1: per-neighbor attention logits -----------------------------
    int id = idxs[lp][jj];
    float prx = p[(long long)id * 3 + 0] - pns[lp][0];
    float pry = p[(long long)id * 3 + 1] - pns[lp][1];
    float prz = p[(long long)id * 3 + 2] - pns[lp][2];
    float l0 = prx * pw1s[0] + pry * pw1s[1] + prz * pw1s[2] + pb1s[0];
    float l1 = prx * pw1s[3] + pry * pw1s[4] + prz * pw1s[5] + pb1s[1];
    float l2 = prx * pw1s[6] + pry * pw1s[7] + prz * pw1s[8] + pb1s[2];
    float h0 = fmaxf(fmaf(l0, pas[0], pbfs[0]), 0.f);
    float h1 = fmaxf(fmaf(l1, pas[1], pbfs[1]), 0.f);
    float h2 = fmaxf(fmaf(l2, pas[2], pbfs[2]), 0.f);
    hs[lp][jj][0] = h0; hs[lp][jj][1] = h1; hs[lp][jj][2] = h2;

    float acc[8];
    #pragma unroll
    for (int o = 0; o < 8; o++) acc[o] = 0.f;

    const float4* xkr   = (const float4*)(g_xk + (long long)id * 64);
    const float4* xqr   = (const float4*)xqs[lp];
    const float4* c04   = (const float4*)pw20s;
    const float4* c14   = (const float4*)pw21s;
    const float4* c24   = (const float4*)pw22s;
    const float4* cb4   = (const float4*)pb2s;
    const float4* aa4   = (const float4*)a1s;
    const float4* bb4   = (const float4*)b1s;
    const float4* w1s4  = (const float4*)w1s;

    #pragma unroll
    for (int g = 0; g < 16; g++) {
        float4 xk4 = xkr[g];
        float4 xq4 = xqr[g];
        float4 c0 = c04[g], c1 = c14[g], c2 = c24[g], cb = cb4[g];
        float4 aa = aa4[g], bb = bb4[g];
        float wv[4];
        wv[0] = fmaxf(fmaf(xk4.x - xq4.x + (c0.x*h0 + c1.x*h1 + c2.x*h2 + cb.x), aa.x, bb.x), 0.f);
        wv[1] = fmaxf(fmaf(xk4.y - xq4.y + (c0.y*h0 + c1.y*h1 + c2.y*h2 + cb.y), aa.y, bb.y), 0.f);
        wv[2] = fmaxf(fmaf(xk4.z - xq4.z + (c0.z*h0 + c1.z*h1 + c2.z*h2 + cb.z), aa.z, bb.z), 0.f);
        wv[3] = fmaxf(fmaf(xk4.w - xq4.w + (c0.w*h0 + c1.w*h1 + c2.w*h2 + cb.w), aa.w, bb.w), 0.f);
        #pragma unroll
        for (int o = 0; o < 8; o++) {
            float4 wr = w1s4[o * 16 + g];
            acc[o] += wr.x * wv[0] + wr.y * wv[1] + wr.z * wv[2] + wr.w * wv[3];
        }
    }

    float y[8];
    #pragma unroll
    for (int o = 0; o < 8; o++)
        y[o] = fmaxf(fmaf(acc[o] + wb1s[o], a2s[o], b2s[o]), 0.f);

    float z[8];
    #pragma unroll
    for (int u = 0; u < 8; u++) {
        float s = wb2s[u];
        #pragma unroll
        for (int o = 0; o < 8; o++) s += y[o] * w2s[u * 8 + o];
        z[u] = s;
    }

    // softmax over the 16 neighbor lanes (xor offsets < 16 keep halves separate)
    #pragma unroll
    for (int u = 0; u < 8; u++) {
        float m = z[u];
        m = fmaxf(m, __shfl_xor_sync(0xffffffffu, m, 1));
        m = fmaxf(m, __shfl_xor_sync(0xffffffffu, m, 2));
        m = fmaxf(m, __shfl_xor_sync(0xffffffffu, m, 4));
        m = fmaxf(m, __shfl_xor_sync(0xffffffffu, m, 8));
        float e = __expf(z[u] - m);
        float s = e;
        s += __shfl_xor_sync(0xffffffffu, s, 1);
        s += __shfl_xor_sync(0xffffffffu, s, 2);
        s += __shfl_xor_sync(0xffffffffu, s, 4);
        s += __shfl_xor_sync(0xffffffffu, s, 8);
        wexps[lp][jj][u] = e / s;
    }
    __syncwarp();

    // ---- Phase 2: weighted reduce, lane = 4 channels ------------------------
    int cb = jj * 4;
    float4 q0 = ((const float4*)pw20s)[jj];
    float4 q1 = ((const float4*)pw21s)[jj];
    float4 q2 = ((const float4*)pw22s)[jj];
    float4 qb = ((const float4*)pb2s)[jj];
    float ox = 0.f, oy = 0.f, oz = 0.f, ow = 0.f;

    #pragma unroll
    for (int j = 0; j < 16; j++) {
        int idj = idxs[lp][j];
        float4 xv4 = *(const float4*)(g_xv + (long long)idj * 64 + cb);
        float hh0 = hs[lp][j][0], hh1 = hs[lp][j][1], hh2 = hs[lp][j][2];
        float4 wn4 = *(const float4*)&wexps[lp][j][(jj & 1) * 4];
        ox += (xv4.x + q0.x*hh0 + q1.x*hh1 + q2.x*hh2 + qb.x) * wn4.x;
        oy += (xv4.y + q0.y*hh0 + q1.y*hh1 + q2.y*hh2 + qb.y) * wn4.y;
        oz += (xv4.z + q0.z*hh0 + q1.z*hh1 + q2.z*hh2 + qb.z) * wn4.z;
        ow += (xv4.w + q0.w*hh0 + q1.w*hh1 + q2.w*hh2 + qb.w) * wn4.w;
    }
    if (n < N)
        *(float4*)&out[(long long)n * 64 + cb] = make_float4(ox, oy, oz, ow);
}

// ---------------------------------------------------------------------------
extern "C" void kernel_launch(void* const* d_in, const int* in_sizes, int n_in,
                              void* d_out, int out_size)
{
    const float* p   = (const float*)d_in[0];
    const float* x   = (const float*)d_in[1];
    const int* idx   = (const int*)d_in[2];     // jax default: int64 request -> int32 array
    const float* Wq  = (const float*)d_in[3];
    const float* bq  = (const float*)d_in[4];
    const float* Wk  = (const float*)d_in[5];
    const float* bk  = (const float*)d_in[6];
    const float* Wv  = (const float*)d_in[7];
    const float* bv  = (const float*)d_in[8];
    const float* pw1 = (const float*)d_in[9];
    const float* pb1 = (const float*)d_in[10];
    const float* pbng = (const float*)d_in[11];
    const float* pbnb = (const float*)d_in[12];
    const float* pbnm = (const float*)d_in[13];
    const float* pbnv = (const float*)d_in[14];
    const float* pw2 = (const float*)d_in[15];
    const float* pb2 = (const float*)d_in[16];
    const float* bn1g = (const float*)d_in[17];
    const float* bn1b = (const float*)d_in[18];
    const float* bn1m = (const float*)d_in[19];
    const float* bn1v = (const float*)d_in[20];
    const float* w1  = (const float*)d_in[21];
    const float* wb1 = (const float*)d_in[22];
    const float* bn2g = (const float*)d_in[23];
    const float* bn2b = (const float*)d_in[24];
    const float* bn2m = (const float*)d_in[25];
    const float* bn2v = (const float*)d_in[26];
    const float* w2  = (const float*)d_in[27];
    const float* wb2 = (const float*)d_in[28];

    int N = in_sizes[1] / 64;

    proj_kernel<<<592, 192>>>(x, Wq, bq, Wk, bk, Wv, bv, N);
    attn_kernel<<<(N + 15) / 16, 256>>>(p, idx,
        pw1, pb1, pbng, pbnb, pbnm, pbnv, pw2, pb2,
        bn1g, bn1b, bn1m, bn1v, w1, wb1,
        bn2g, bn2b, bn2m, bn2v, w2, wb2,
        (float*)d_out, N);
}

// round 6
// speedup vs baseline: 1.2938x; 1.2938x over previous
#include <cuda_runtime.h>

#define NMAX 100000
#define EPSF 1e-5f

// q/k/v projection scratch (device globals: allocation-free).
__device__ float g_xq[NMAX * 64];
__device__ float g_xk[NMAX * 64];
__device__ float g_xv[NMAX * 64];

// ---------------------------------------------------------------------------
// Folded constants, staged on device then copied into __constant__.
// ---------------------------------------------------------------------------
struct CParams {
    float4 w1[128];                         // w_w1 [o][4g..4g+3] (raw layout)
    float4 A[16];                           // bn1 scale folded, per channel
    float4 T0[16], T1[16], T2[16], TB[16];  // A*pw2 cols, A*pb2 + b1
    float4 R0[16], R1[16], R2[16], RB[16];  // raw pw2 cols, raw pb2
    float a2[8], c2f[8];                    // y = relu(a2*acc + c2f)
    float w2[64];
    float wb2[8];
    float fw1[9], fb1[3];                   // folded p-MLP layer1 (pa*pw1, pa*pb1+pbf)
    float pad[4];
};
__device__ CParams g_stage;
__constant__ CParams c_P;

__global__ void prep_kernel(
    const float* __restrict__ pw1, const float* __restrict__ pb1,
    const float* __restrict__ pbng, const float* __restrict__ pbnb,
    const float* __restrict__ pbnm, const float* __restrict__ pbnv,
    const float* __restrict__ pw2, const float* __restrict__ pb2,
    const float* __restrict__ bn1g, const float* __restrict__ bn1b,
    const float* __restrict__ bn1m, const float* __restrict__ bn1v,
    const float* __restrict__ w1,  const float* __restrict__ wb1,
    const float* __restrict__ bn2g, const float* __restrict__ bn2b,
    const float* __restrict__ bn2m, const float* __restrict__ bn2v,
    const float* __restrict__ w2,  const float* __restrict__ wb2)
{
    int t = threadIdx.x;  // 64 threads
    if (t < 64) {
        float a  = bn1g[t] * rsqrtf(bn1v[t] + EPSF);
        float b1 = bn1b[t] - bn1m[t] * a;
        float r0 = pw2[t * 3 + 0], r1 = pw2[t * 3 + 1], r2 = pw2[t * 3 + 2];
        float rb = pb2[t];
        ((float*)g_stage.A )[t] = a;
        ((float*)g_stage.T0)[t] = a * r0;
        ((float*)g_stage.T1)[t] = a * r1;
        ((float*)g_stage.T2)[t] = a * r2;
        ((float*)g_stage.TB)[t] = a * rb + b1;
        ((float*)g_stage.R0)[t] = r0;
        ((float*)g_stage.R1)[t] = r1;
        ((float*)g_stage.R2)[t] = r2;
        ((float*)g_stage.RB)[t] = rb;
        g_stage.w2[t] = w2[t];
    }
    for (int i = t; i < 512; i += 64) ((float*)g_stage.w1)[i] = w1[i];
    if (t < 8) {
        float a2 = bn2g[t] * rsqrtf(bn2v[t] + EPSF);
        g_stage.a2[t]  = a2;
        g_stage.c2f[t] = a2 * wb1[t] + (bn2b[t] - bn2m[t] * a2);
        g_stage.wb2[t] = wb2[t];
    }
    if (t < 3) {
        float pa = pbng[t] * rsqrtf(pbnv[t] + EPSF);
        g_stage.fw1[t * 3 + 0] = pa * pw1[t * 3 + 0];
        g_stage.fw1[t * 3 + 1] = pa * pw1[t * 3 + 1];
        g_stage.fw1[t * 3 + 2] = pa * pw1[t * 3 + 2];
        g_stage.fb1[t] = pa * pb1[t] + (pbnb[t] - pbnm[t] * pa);
    }
}

// ---------------------------------------------------------------------------
// Kernel A: q/k/v projection. Block = 64 points, specialized per q/k/v via
// blockIdx.y. x tile staged in shared; weights transposed (pad 68) in shared.
// Thread = (4 out channels, 4 points).
// ---------------------------------------------------------------------------
__global__ __launch_bounds__(256) void proj2(
    const float* __restrict__ x,
    const float* __restrict__ Wq, const float* __restrict__ bq,
    const float* __restrict__ Wk, const float* __restrict__ bk,
    const float* __restrict__ Wv, const float* __restrict__ bv,
    int N)
{
    const float* W; const float* b; float* dst;
    if (blockIdx.y == 0)      { W = Wq; b = bq; dst = g_xq; }
    else if (blockIdx.y == 1) { W = Wk; b = bk; dst = g_xk; }
    else                      { W = Wv; b = bv; dst = g_xv; }

    __shared__ __align__(16) float Wt[64 * 68];
    __shared__ __align__(16) float xs[64 * 64];
    int t = threadIdx.x;

    for (int i = t; i < 4096; i += 256) {
        int o = i >> 6, c = i & 63;
        Wt[c * 68 + o] = W[i];
    }
    int tile0 = blockIdx.x * 64;
    for (int i = t; i < 1024; i += 256) {
        int f = i * 4;
        int pl = f >> 6, c = f & 63;
        int pt = tile0 + pl; pt = (pt < N) ? pt : N - 1;
        *(float4*)&xs[f] = *(const float4*)&x[(size_t)pt * 64 + c];
    }
    __syncthreads();

    int og = t & 15, pg = t >> 4;
    int o0 = og * 4;
    float4 bias = *(const float4*)&b[o0];

    float acc[4][4];
    #pragma unroll
    for (int a = 0; a < 4; a++)
        #pragma unroll
        for (int bb = 0; bb < 4; bb++) acc[a][bb] = 0.f;

    #pragma unroll
    for (int c4 = 0; c4 < 16; c4++) {
        float4 wv[4];
        #pragma unroll
        for (int k = 0; k < 4; k++)
            wv[k] = *(const float4*)&Wt[(4 * c4 + k) * 68 + o0];
        #pragma unroll
        for (int pp = 0; pp < 4; pp++) {
            float4 x4 = *(const float4*)&xs[(pg * 4 + pp) * 64 + 4 * c4];
            acc[pp][0] = fmaf(x4.x, wv[0].x, fmaf(x4.y, wv[1].x, fmaf(x4.z, wv[2].x, fmaf(x4.w, wv[3].x, acc[pp][0]))));
            acc[pp][1] = fmaf(x4.x, wv[0].y, fmaf(x4.y, wv[1].y, fmaf(x4.z, wv[2].y, fmaf(x4.w, wv[3].y, acc[pp][1]))));
            acc[pp][2] = fmaf(x4.x, wv[0].z, fmaf(x4.y, wv[1].z, fmaf(x4.z, wv[2].z, fmaf(x4.w, wv[3].z, acc[pp][2]))));
            acc[pp][3] = fmaf(x4.x, wv[0].w, fmaf(x4.y, wv[1].w, fmaf(x4.z, wv[2].w, fmaf(x4.w, wv[3].w, acc[pp][3]))));
        }
    }
    #pragma unroll
    for (int pp = 0; pp < 4; pp++) {
        int pt = tile0 + pg * 4 + pp;
        if (pt < N) {
            float4 v = make_float4(acc[pp][0] + bias.x, acc[pp][1] + bias.y,
                                   acc[pp][2] + bias.z, acc[pp][3] + bias.w);
            *(float4*)&dst[(size_t)pt * 64 + o0] = v;
        }
    }
}

// ---------------------------------------------------------------------------
// Kernel B: fused attention. Block = 8 points, 128 threads, fully warp-local
// (each warp owns 2 points). Phase A: thread=(point, 4ch) computes BN-folded
// v into swizzled vbuf (coalesced gather). Phase B: thread=(point, neighbor)
// does 64->8 projection (w1 from __constant__), BN2/MLP/softmax. Phase 2:
// thread=(point, 4ch) weighted reduce (coalesced xv gather).
// ---------------------------------------------------------------------------
__global__ __launch_bounds__(128) void attn2(
    const float* __restrict__ p, const int* __restrict__ idx,
    float* __restrict__ out, int N)
{
    __shared__ __align__(16) float4 vbuf[8][16][16];
    __shared__ __align__(16) float  wex[8][16][12];
    __shared__ float hs[8][16][4];
    __shared__ int   idxs[8][16];
    __shared__ float pns[8][4];

    int t = threadIdx.x, lane = t & 31, wid = t >> 5;
    int n0 = blockIdx.x * 8;

    int lpA = t >> 4, sub = t & 15;     // mapping for prologue / phase A / phase 2
    int nA  = n0 + lpA;
    int nAc = (nA < N) ? nA : N - 1;

    // prologue: indices, center coords, h-MLP
    int id0 = idx[(size_t)nAc * 16 + sub];
    id0 = (id0 < 0) ? 0 : ((id0 >= N) ? N - 1 : id0);
    idxs[lpA][sub] = id0;
    if (lane < 6) {
        int pp = wid * 2 + lane / 3, d = lane % 3;
        int np = n0 + pp; np = (np < N) ? np : N - 1;
        pns[pp][d] = p[(size_t)np * 3 + d];
    }
    __syncwarp();
    {
        float prx = p[(size_t)id0 * 3 + 0] - pns[lpA][0];
        float pry = p[(size_t)id0 * 3 + 1] - pns[lpA][1];
        float prz = p[(size_t)id0 * 3 + 2] - pns[lpA][2];
        hs[lpA][sub][0] = fmaxf(fmaf(prx, c_P.fw1[0], fmaf(pry, c_P.fw1[1], fmaf(prz, c_P.fw1[2], c_P.fb1[0]))), 0.f);
        hs[lpA][sub][1] = fmaxf(fmaf(prx, c_P.fw1[3], fmaf(pry, c_P.fw1[4], fmaf(prz, c_P.fw1[5], c_P.fb1[1]))), 0.f);
        hs[lpA][sub][2] = fmaxf(fmaf(prx, c_P.fw1[6], fmaf(pry, c_P.fw1[7], fmaf(prz, c_P.fw1[8], c_P.fb1[2]))), 0.f);
    }
    // per-thread channel constants (one-time divergent const loads)
    float4 Ac = c_P.A[sub];
    float4 T0 = c_P.T0[sub], T1 = c_P.T1[sub], T2 = c_P.T2[sub];
    float4 TBc = c_P.TB[sub];
    float4 xq4 = *(const float4*)&g_xq[(size_t)nAc * 64 + sub * 4];
    float4 TBm = make_float4(TBc.x - Ac.x * xq4.x, TBc.y - Ac.y * xq4.y,
                             TBc.z - Ac.z * xq4.z, TBc.w - Ac.w * xq4.w);
    __syncwarp();

    // ---- Phase A: v = relu(A*xk + T.h + TBm), staged to swizzled vbuf ------
    #pragma unroll
    for (int j = 0; j < 16; j++) {
        int id = idxs[lpA][j];
        float h0 = hs[lpA][j][0], h1 = hs[lpA][j][1], h2 = hs[lpA][j][2];
        float4 xk4 = *(const float4*)&g_xk[(size_t)id * 64 + sub * 4];
        float4 v;
        v.x = fmaxf(fmaf(Ac.x, xk4.x, fmaf(T2.x, h2, fmaf(T1.x, h1, fmaf(T0.x, h0, TBm.x)))), 0.f);
        v.y = fmaxf(fmaf(Ac.y, xk4.y, fmaf(T2.y, h2, fmaf(T1.y, h1, fmaf(T0.y, h0, TBm.y)))), 0.f);
        v.z = fmaxf(fmaf(Ac.z, xk4.z, fmaf(T2.z, h2, fmaf(T1.z, h1, fmaf(T0.z, h0, TBm.z)))), 0.f);
        v.w = fmaxf(fmaf(Ac.w, xk4.w, fmaf(T2.w, h2, fmaf(T1.w, h1, fmaf(T0.w, h0, TBm.w)))), 0.f);
        vbuf[lpA][j][(sub + j) & 15] = v;
    }
    __syncwarp();

    // ---- Phase B: 64->8 projection + BN2 + w2 + softmax --------------------
    int lpB = wid * 2 + (lane >> 4), jj = lane & 15;
    float acc[8];
    #pragma unroll
    for (int o = 0; o < 8; o++) acc[o] = 0.f;
    #pragma unroll
    for (int g = 0; g < 16; g++) {
        float4 v4 = vbuf[lpB][jj][(g + jj) & 15];
        #pragma unroll
        for (int o = 0; o < 8; o++) {
            float4 w = c_P.w1[o * 16 + g];
            acc[o] = fmaf(w.x, v4.x, fmaf(w.y, v4.y, fmaf(w.z, v4.z, fmaf(w.w, v4.w, acc[o]))));
        }
    }
    float y[8], z[8];
    #pragma unroll
    for (int o = 0; o < 8; o++)
        y[o] = fmaxf(fmaf(c_P.a2[o], acc[o], c_P.c2f[o]), 0.f);
    #pragma unroll
    for (int u = 0; u < 8; u++) {
        float s = c_P.wb2[u];
        #pragma unroll
        for (int o = 0; o < 8; o++) s = fmaf(y[o], c_P.w2[u * 8 + o], s);
        z[u] = s;
    }
    float e[8];
    #pragma unroll
    for (int u = 0; u < 8; u++) {
        float m = z[u];
        m = fmaxf(m, __shfl_xor_sync(0xffffffffu, m, 1));
        m = fmaxf(m, __shfl_xor_sync(0xffffffffu, m, 2));
        m = fmaxf(m, __shfl_xor_sync(0xffffffffu, m, 4));
        m = fmaxf(m, __shfl_xor_sync(0xffffffffu, m, 8));
        float ev = __expf(z[u] - m);
        float s = ev;
        s += __shfl_xor_sync(0xffffffffu, s, 1);
        s += __shfl_xor_sync(0xffffffffu, s, 2);
        s += __shfl_xor_sync(0xffffffffu, s, 4);
        s += __shfl_xor_sync(0xffffffffu, s, 8);
        e[u] = ev * __frcp_rn(s);
    }
    *(float4*)&wex[lpB][jj][0] = make_float4(e[0], e[1], e[2], e[3]);
    *(float4*)&wex[lpB][jj][4] = make_float4(e[4], e[5], e[6], e[7]);
    __syncwarp();

    // ---- Phase 2: out_c = sum_j (xv_c + p_r,c) * wex[j][c%8] ---------------
    float4 q0 = c_P.R0[sub], q1 = c_P.R1[sub], q2 = c_P.R2[sub], qb = c_P.RB[sub];
    float ox = 0.f, oy = 0.f, oz = 0.f, ow = 0.f;
    #pragma unroll
    for (int j = 0; j < 16; j++) {
        int id = idxs[lpA][j];
        float h0 = hs[lpA][j][0], h1 = hs[lpA][j][1], h2 = hs[lpA][j][2];
        float4 xv4 = *(const float4*)&g_xv[(size_t)id * 64 + sub * 4];
        float4 wn4 = *(const float4*)&wex[lpA][j][(sub & 1) * 4];
        float rx = fmaf(q0.x, h0, fmaf(q1.x, h1, fmaf(q2.x, h2, qb.x)));
        float ry = fmaf(q0.y, h0, fmaf(q1.y, h1, fmaf(q2.y, h2, qb.y)));
        float rz = fmaf(q0.z, h0, fmaf(q1.z, h1, fmaf(q2.z, h2, qb.z)));
        float rw = fmaf(q0.w, h0, fmaf(q1.w, h1, fmaf(q2.w, h2, qb.w)));
        ox = fmaf(xv4.x + rx, wn4.x, ox);
        oy = fmaf(xv4.y + ry, wn4.y, oy);
        oz = fmaf(xv4.z + rz, wn4.z, oz);
        ow = fmaf(xv4.w + rw, wn4.w, ow);
    }
    if (nA < N)
        *(float4*)&out[(size_t)nA * 64 + sub * 4] = make_float4(ox, oy, oz, ow);
}

// ---------------------------------------------------------------------------
extern "C" void kernel_launch(void* const* d_in, const int* in_sizes, int n_in,
                              void* d_out, int out_size)
{
    const float* p   = (const float*)d_in[0];
    const float* x   = (const float*)d_in[1];
    const int* idx   = (const int*)d_in[2];
    const float* Wq  = (const float*)d_in[3];
    const float* bq  = (const float*)d_in[4];
    const float* Wk  = (const float*)d_in[5];
    const float* bk  = (const float*)d_in[6];
    const float* Wv  = (const float*)d_in[7];
    const float* bv  = (const float*)d_in[8];
    const float* pw1 = (const float*)d_in[9];
    const float* pb1 = (const float*)d_in[10];
    const float* pbng = (const float*)d_in[11];
    const float* pbnb = (const float*)d_in[12];
    const float* pbnm = (const float*)d_in[13];
    const float* pbnv = (const float*)d_in[14];
    const float* pw2 = (const float*)d_in[15];
    const float* pb2 = (const float*)d_in[16];
    const float* bn1g = (const float*)d_in[17];
    const float* bn1b = (const float*)d_in[18];
    const float* bn1m = (const float*)d_in[19];
    const float* bn1v = (const float*)d_in[20];
    const float* w1  = (const float*)d_in[21];
    const float* wb1 = (const float*)d_in[22];
    const float* bn2g = (const float*)d_in[23];
    const float* bn2b = (const float*)d_in[24];
    const float* bn2m = (const float*)d_in[25];
    const float* bn2v = (const float*)d_in[26];
    const float* w2  = (const float*)d_in[27];
    const float* wb2 = (const float*)d_in[28];

    int N = in_sizes[1] / 64;

    prep_kernel<<<1, 64>>>(pw1, pb1, pbng, pbnb, pbnm, pbnv, pw2, pb2,
                           bn1g, bn1b, bn1m, bn1v, w1, wb1,
                           bn2g, bn2b, bn2m, bn2v, w2, wb2);
    void* sp = nullptr;
    cudaGetSymbolAddress(&sp, g_stage);
    cudaMemcpyToSymbolAsync(c_P, sp, sizeof(CParams), 0,
                            cudaMemcpyDeviceToDevice, 0);

    dim3 pgrid((N + 63) / 64, 3);
    proj2<<<pgrid, 256>>>(x, Wq, bq, Wk, bk, Wv, bv, N);
    attn2<<<(N + 7) / 8, 128>>>(p, idx, (float*)d_out, N);
}

// round 8
// speedup vs baseline: 1.3622x; 1.0529x over previous
#include <cuda_runtime.h>
#include <cuda_fp16.h>

#define NMAX 100000
#define EPSF 1e-5f

// q/k/v projection scratch in fp16 (device globals: allocation-free).
// Row = 32 half2 = 64 channels = 128 bytes (one L2/L1 line per row!).
__device__ __half2 g_xq[NMAX * 32];
__device__ __half2 g_xk[NMAX * 32];
__device__ __half2 g_xv[NMAX * 32];

__device__ __forceinline__ float4 ldg_h4(const __half2* __restrict__ base,
                                         size_t row, int sub) {
    uint2 u = *(const uint2*)(base + row * 32 + sub * 2);
    __half2 a = *(__half2*)&u.x, b = *(__half2*)&u.y;
    float2 fa = __half22float2(a), fb = __half22float2(b);
    return make_float4(fa.x, fa.y, fb.x, fb.y);
}

// ---------------------------------------------------------------------------
// Folded constants, staged on device then copied into __constant__.
// ---------------------------------------------------------------------------
struct CParams {
    float4 w1[128];                         // w_w1 [o][4g..4g+3] (raw layout)
    float4 A[16];                           // bn1 scale folded, per channel
    float4 T0[16], T1[16], T2[16], TB[16];  // A*pw2 cols, A*pb2 + b1
    float4 R0[16], R1[16], R2[16], RB[16];  // raw pw2 cols, raw pb2
    float a2[8], c2f[8];                    // y = relu(a2*acc + c2f)
    float w2[64];
    float wb2[8];
    float fw1[9], fb1[3];                   // folded p-MLP layer1
    float pad[4];
};
__device__ CParams g_stage;
__constant__ CParams c_P;

__global__ void prep_kernel(
    const float* __restrict__ pw1, const float* __restrict__ pb1,
    const float* __restrict__ pbng, const float* __restrict__ pbnb,
    const float* __restrict__ pbnm, const float* __restrict__ pbnv,
    const float* __restrict__ pw2, const float* __restrict__ pb2,
    const float* __restrict__ bn1g, const float* __restrict__ bn1b,
    const float* __restrict__ bn1m, const float* __restrict__ bn1v,
    const float* __restrict__ w1,  const float* __restrict__ wb1,
    const float* __restrict__ bn2g, const float* __restrict__ bn2b,
    const float* __restrict__ bn2m, const float* __restrict__ bn2v,
    const float* __restrict__ w2,  const float* __restrict__ wb2)
{
    int t = threadIdx.x;  // 64 threads
    if (t < 64) {
        float a  = bn1g[t] * rsqrtf(bn1v[t] + EPSF);
        float b1 = bn1b[t] - bn1m[t] * a;
        float r0 = pw2[t * 3 + 0], r1 = pw2[t * 3 + 1], r2 = pw2[t * 3 + 2];
        float rb = pb2[t];
        ((float*)g_stage.A )[t] = a;
        ((float*)g_stage.T0)[t] = a * r0;
        ((float*)g_stage.T1)[t] = a * r1;
        ((float*)g_stage.T2)[t] = a * r2;
        ((float*)g_stage.TB)[t] = a * rb + b1;
        ((float*)g_stage.R0)[t] = r0;
        ((float*)g_stage.R1)[t] = r1;
        ((float*)g_stage.R2)[t] = r2;
        ((float*)g_stage.RB)[t] = rb;
        g_stage.w2[t] = w2[t];
    }
    for (int i = t; i < 512; i += 64) ((float*)g_stage.w1)[i] = w1[i];
    if (t < 8) {
        float a2 = bn2g[t] * rsqrtf(bn2v[t] + EPSF);
        g_stage.a2[t]  = a2;
        g_stage.c2f[t] = a2 * wb1[t] + (bn2b[t] - bn2m[t] * a2);
        g_stage.wb2[t] = wb2[t];
    }
    if (t < 3) {
        float pa = pbng[t] * rsqrtf(pbnv[t] + EPSF);
        g_stage.fw1[t * 3 + 0] = pa * pw1[t * 3 + 0];
        g_stage.fw1[t * 3 + 1] = pa * pw1[t * 3 + 1];
        g_stage.fw1[t * 3 + 2] = pa * pw1[t * 3 + 2];
        g_stage.fb1[t] = pa * pb1[t] + (pbnb[t] - pbnm[t] * pa);
    }
}

// ---------------------------------------------------------------------------
// Kernel A: q/k/v projection, fp16 output. Block = 64 points, specialized per
// q/k/v via blockIdx.y. Thread = (4 out channels, 4 points).
// ---------------------------------------------------------------------------
__global__ __launch_bounds__(256) void proj2(
    const float* __restrict__ x,
    const float* __restrict__ Wq, const float* __restrict__ bq,
    const float* __restrict__ Wk, const float* __restrict__ bk,
    const float* __restrict__ Wv, const float* __restrict__ bv,
    int N)
{
    const float* W; const float* b; __half2* dst;
    if (blockIdx.y == 0)      { W = Wq; b = bq; dst = g_xq; }
    else if (blockIdx.y == 1) { W = Wk; b = bk; dst = g_xk; }
    else                      { W = Wv; b = bv; dst = g_xv; }

    __shared__ __align__(16) float Wt[64 * 68];
    __shared__ __align__(16) float xs[64 * 64];
    int t = threadIdx.x;

    for (int i = t; i < 4096; i += 256) {
        int o = i >> 6, c = i & 63;
        Wt[c * 68 + o] = W[i];
    }
    int tile0 = blockIdx.x * 64;
    for (int i = t; i < 1024; i += 256) {
        int f = i * 4;
        int pl = f >> 6, c = f & 63;
        int pt = tile0 + pl; pt = (pt < N) ? pt : N - 1;
        *(float4*)&xs[f] = *(const float4*)&x[(size_t)pt * 64 + c];
    }
    __syncthreads();

    int og = t & 15, pg = t >> 4;
    int o0 = og * 4;
    float4 bias = *(const float4*)&b[o0];

    float acc[4][4];
    #pragma unroll
    for (int a = 0; a < 4; a++)
        #pragma unroll
        for (int bb = 0; bb < 4; bb++) acc[a][bb] = 0.f;

    #pragma unroll
    for (int c4 = 0; c4 < 16; c4++) {
        float4 wv[4];
        #pragma unroll
        for (int k = 0; k < 4; k++)
            wv[k] = *(const float4*)&Wt[(4 * c4 + k) * 68 + o0];
        #pragma unroll
        for (int pp = 0; pp < 4; pp++) {
            float4 x4 = *(const float4*)&xs[(pg * 4 + pp) * 64 + 4 * c4];
            acc[pp][0] = fmaf(x4.x, wv[0].x, fmaf(x4.y, wv[1].x, fmaf(x4.z, wv[2].x, fmaf(x4.w, wv[3].x, acc[pp][0]))));
            acc[pp][1] = fmaf(x4.x, wv[0].y, fmaf(x4.y, wv[1].y, fmaf(x4.z, wv[2].y, fmaf(x4.w, wv[3].y, acc[pp][1]))));
            acc[pp][2] = fmaf(x4.x, wv[0].z, fmaf(x4.y, wv[1].z, fmaf(x4.z, wv[2].z, fmaf(x4.w, wv[3].z, acc[pp][2]))));
            acc[pp][3] = fmaf(x4.x, wv[0].w, fmaf(x4.y, wv[1].w, fmaf(x4.z, wv[2].w, fmaf(x4.w, wv[3].w, acc[pp][3]))));
        }
    }
    #pragma unroll
    for (int pp = 0; pp < 4; pp++) {
        int pt = tile0 + pg * 4 + pp;
        if (pt < N) {
            __half2 h0 = __floats2half2_rn(acc[pp][0] + bias.x, acc[pp][1] + bias.y);
            __half2 h1 = __floats2half2_rn(acc[pp][2] + bias.z, acc[pp][3] + bias.w);
            uint2 st;
            st.x = *(unsigned int*)&h0;
            st.y = *(unsigned int*)&h1;
            *(uint2*)(dst + (size_t)pt * 32 + og * 2) = st;
        }
    }
}

// ---------------------------------------------------------------------------
// Kernel B: fused attention. Block = 8 points, 128 threads, warp-local.
// ---------------------------------------------------------------------------
__global__ __launch_bounds__(128) void attn2(
    const float* __restrict__ p, const int* __restrict__ idx,
    float* __restrict__ out, int N)
{
    __shared__ __align__(16) float4 vbuf[8][16][16];
    __shared__ __align__(16) float  wex[8][16][12];
    __shared__ float hs[8][16][4];
    __shared__ int   idxs[8][16];
    __shared__ float pns[8][4];

    int t = threadIdx.x, lane = t & 31, wid = t >> 5;
    int n0 = blockIdx.x * 8;

    int lpA = t >> 4, sub = t & 15;
    int nA  = n0 + lpA;
    int nAc = (nA < N) ? nA : N - 1;

    // prologue: indices, center coords, h-MLP
    int id0 = idx[(size_t)nAc * 16 + sub];
    id0 = (id0 < 0) ? 0 : ((id0 >= N) ? N - 1 : id0);
    idxs[lpA][sub] = id0;
    if (lane < 6) {
        int pp = wid * 2 + lane / 3, d = lane % 3;
        int np = n0 + pp; np = (np < N) ? np : N - 1;
        pns[pp][d] = p[(size_t)np * 3 + d];
    }
    __syncwarp();
    {
        float prx = p[(size_t)id0 * 3 + 0] - pns[lpA][0];
        float pry = p[(size_t)id0 * 3 + 1] - pns[lpA][1];
        float prz = p[(size_t)id0 * 3 + 2] - pns[lpA][2];
        hs[lpA][sub][0] = fmaxf(fmaf(prx, c_P.fw1[0], fmaf(pry, c_P.fw1[1], fmaf(prz, c_P.fw1[2], c_P.fb1[0]))), 0.f);
        hs[lpA][sub][1] = fmaxf(fmaf(prx, c_P.fw1[3], fmaf(pry, c_P.fw1[4], fmaf(prz, c_P.fw1[5], c_P.fb1[1]))), 0.f);
        hs[lpA][sub][2] = fmaxf(fmaf(prx, c_P.fw1[6], fmaf(pry, c_P.fw1[7], fmaf(prz, c_P.fw1[8], c_P.fb1[2]))), 0.f);
    }
    float4 Ac = c_P.A[sub];
    float4 T0 = c_P.T0[sub], T1 = c_P.T1[sub], T2 = c_P.T2[sub];
    float4 TBc = c_P.TB[sub];
    float4 xq4 = ldg_h4(g_xq, (size_t)nAc, sub);
    float4 TBm = make_float4(TBc.x - Ac.x * xq4.x, TBc.y - Ac.y * xq4.y,
                             TBc.z - Ac.z * xq4.z, TBc.w - Ac.w * xq4.w);
    __syncwarp();

    // ---- Phase A: v = relu(A*xk + T.h + TBm), staged to swizzled vbuf ------
    #pragma unroll
    for (int j = 0; j < 16; j++) {
        int id = idxs[lpA][j];
        float h0 = hs[lpA][j][0], h1 = hs[lpA][j][1], h2 = hs[lpA][j][2];
        float4 xk4 = ldg_h4(g_xk, (size_t)id, sub);
        float4 v;
        v.x = fmaxf(fmaf(Ac.x, xk4.x, fmaf(T2.x, h2, fmaf(T1.x, h1, fmaf(T0.x, h0, TBm.x)))), 0.f);
        v.y = fmaxf(fmaf(Ac.y, xk4.y, fmaf(T2.y, h2, fmaf(T1.y, h1, fmaf(T0.y, h0, TBm.y)))), 0.f);
        v.z = fmaxf(fmaf(Ac.z, xk4.z, fmaf(T2.z, h2, fmaf(T1.z, h1, fmaf(T0.z, h0, TBm.z)))), 0.f);
        v.w = fmaxf(fmaf(Ac.w, xk4.w, fmaf(T2.w, h2, fmaf(T1.w, h1, fmaf(T0.w, h0, TBm.w)))), 0.f);
        vbuf[lpA][j][(sub + j) & 15] = v;
    }
    __syncwarp();

    // ---- Phase B: 64->8 projection + BN2 + w2 + softmax --------------------
    int lpB = wid * 2 + (lane >> 4), jj = lane & 15;
    float acc[8];
    #pragma unroll
    for (int o = 0; o < 8; o++) acc[o] = 0.f;
    #pragma unroll
    for (int g = 0; g < 16; g++) {
        float4 v4 = vbuf[lpB][jj][(g + jj) & 15];
        #pragma unroll
        for (int o = 0; o < 8; o++) {
            float4 w = c_P.w1[o * 16 + g];
            acc[o] = fmaf(w.x, v4.x, fmaf(w.y, v4.y, fmaf(w.z, v4.z, fmaf(w.w, v4.w, acc[o]))));
        }
    }
    float y[8], z[8];
    #pragma unroll
    for (int o = 0; o < 8; o++)
        y[o] = fmaxf(fmaf(c_P.a2[o], acc[o], c_P.c2f[o]), 0.f);
    #pragma unroll
    for (int u = 0; u < 8; u++) {
        float s = c_P.wb2[u];
        #pragma unroll
        for (int o = 0; o < 8; o++) s = fmaf(y[o], c_P.w2[u * 8 + o], s);
        z[u] = s;
    }
    float e[8];
    #pragma unroll
    for (int u = 0; u < 8; u++) {
        float m = z[u];
        m = fmaxf(m, __shfl_xor_sync(0xffffffffu, m, 1));
        m = fmaxf(m, __shfl_xor_sync(0xffffffffu, m, 2));
        m = fmaxf(m, __shfl_xor_sync(0xffffffffu, m, 4));
        m = fmaxf(m, __shfl_xor_sync(0xffffffffu, m, 8));
        float ev = __expf(z[u] - m);
        float s = ev;
        s += __shfl_xor_sync(0xffffffffu, s, 1);
        s += __shfl_xor_sync(0xffffffffu, s, 2);
        s += __shfl_xor_sync(0xffffffffu, s, 4);
        s += __shfl_xor_sync(0xffffffffu, s, 8);
        e[u] = ev * __frcp_rn(s);
    }
    *(float4*)&wex[lpB][jj][0] = make_float4(e[0], e[1], e[2], e[3]);
    *(float4*)&wex[lpB][jj][4] = make_float4(e[4], e[5], e[6], e[7]);
    __syncwarp();

    // ---- Phase 2: out_c = sum_j (xv_c + p_r,c) * wex[j][c%8] ---------------
    float4 q0 = c_P.R0[sub], q1 = c_P.R1[sub], q2 = c_P.R2[sub], qb = c_P.RB[sub];
    float ox = 0.f, oy = 0.f, oz = 0.f, ow = 0.f;
    #pragma unroll
    for (int j = 0; j < 16; j++) {
        int id = idxs[lpA][j];
        float h0 = hs[lpA][j][0], h1 = hs[lpA][j][1], h2 = hs[lpA][j][2];
        float4 xv4 = ldg_h4(g_xv, (size_t)id, sub);
        float4 wn4 = *(const float4*)&wex[lpA][j][(sub & 1) * 4];
        float rx = fmaf(q0.x, h0, fmaf(q1.x, h1, fmaf(q2.x, h2, qb.x)));
        float ry = fmaf(q0.y, h0, fmaf(q1.y, h1, fmaf(q2.y, h2, qb.y)));
        float rz = fmaf(q0.z, h0, fmaf(q1.z, h1, fmaf(q2.z, h2, qb.z)));
        float rw = fmaf(q0.w, h0, fmaf(q1.w, h1, fmaf(q2.w, h2, qb.w)));
        ox = fmaf(xv4.x + rx, wn4.x, ox);
        oy = fmaf(xv4.y + ry, wn4.y, oy);
        oz = fmaf(xv4.z + rz, wn4.z, oz);
        ow = fmaf(xv4.w + rw, wn4.w, ow);
    }
    if (nA < N)
        *(float4*)&out[(size_t)nA * 64 + sub * 4] = make_float4(ox, oy, oz, ow);
}

// ---------------------------------------------------------------------------
extern "C" void kernel_launch(void* const* d_in, const int* in_sizes, int n_in,
                              void* d_out, int out_size)
{
    const float* p   = (const float*)d_in[0];
    const float* x   = (const float*)d_in[1];
    const int* idx   = (const int*)d_in[2];
    const float* Wq  = (const float*)d_in[3];
    const float* bq  = (const float*)d_in[4];
    const float* Wk  = (const float*)d_in[5];
    const float* bk  = (const float*)d_in[6];
    const float* Wv  = (const float*)d_in[7];
    const float* bv  = (const float*)d_in[8];
    const float* pw1 = (const float*)d_in[9];
    const float* pb1 = (const float*)d_in[10];
    const float* pbng = (const float*)d_in[11];
    const float* pbnb = (const float*)d_in[12];
    const float* pbnm = (const float*)d_in[13];
    const float* pbnv = (const float*)d_in[14];
    const float* pw2 = (const float*)d_in[15];
    const float* pb2 = (const float*)d_in[16];
    const float* bn1g = (const float*)d_in[17];
    const float* bn1b = (const float*)d_in[18];
    const float* bn1m = (const float*)d_in[19];
    const float* bn1v = (const float*)d_in[20];
    const float* w1  = (const float*)d_in[21];
    const float* wb1 = (const float*)d_in[22];
    const float* bn2g = (const float*)d_in[23];
    const float* bn2b = (const float*)d_in[24];
    const float* bn2m = (const float*)d_in[25];
    const float* bn2v = (const float*)d_in[26];
    const float* w2  = (const float*)d_in[27];
    const float* wb2 = (const float*)d_in[28];

    int N = in_sizes[1] / 64;

    prep_kernel<<<1, 64>>>(pw1, pb1, pbng, pbnb, pbnm, pbnv, pw2, pb2,
                           bn1g, bn1b, bn1m, bn1v, w1, wb1,
                           bn2g, bn2b, bn2m, bn2v, w2, wb2);
    void* sp = nullptr;
    cudaGetSymbolAddress(&sp, g_stage);
    cudaMemcpyToSymbolAsync(c_P, sp, sizeof(CParams), 0,
                            cudaMemcpyDeviceToDevice, 0);

    dim3 pgrid((N + 63) / 64, 3);
    proj2<<<pgrid, 256>>>(x, Wq, bq, Wk, bk, Wv, bv, N);
    attn2<<<(N + 7) / 8, 128>>>(p, idx, (float*)d_out, N);
}